// round 6
// baseline (speedup 1.0000x reference)
#include <cuda_runtime.h>
#include <cstdint>

#define B 16
#define CIN 16
#define DD 16
#define HH 128
#define WW 128
#define COUT 64
#define HW (HH*WW)

// ---- device scratch ----
__device__ float g_s[B*CIN*HW];          // depth-summed x
__device__ float g_wbh[3*3*48*64];       // weights tf32-hi [kh][kw][ci][co], sign folded
__device__ float g_wbl[3*3*48*64];       // tf32 lo residuals

__device__ __forceinline__ float to_tf32(float v){
    float h; asm("cvt.rna.tf32.f32 %0, %1;" : "=f"(h) : "f"(v)); return h;
}

// m16n8k8 row.col tf32 MMA, accumulate in place
__device__ __forceinline__ void mma8(float& d0, float& d1, float& d2, float& d3,
                                     uint32_t a0, uint32_t a1, uint32_t a2, uint32_t a3,
                                     uint32_t b0, uint32_t b1){
    asm volatile("mma.sync.aligned.m16n8k8.row.col.f32.tf32.tf32.f32 "
        "{%0,%1,%2,%3},{%4,%5,%6,%7},{%8,%9},{%0,%1,%2,%3};"
        : "+f"(d0), "+f"(d1), "+f"(d2), "+f"(d3)
        : "r"(a0), "r"(a1), "r"(a2), "r"(a3), "r"(b0), "r"(b1));
}

// ============================================================
// Kernel A: depth sum + weight hi/lo prep (merged)
// ============================================================
#define DS_BLOCKS (B*CIN*(HW/4)/256)      // 8192
__global__ void prep_all(const float* __restrict__ x,
                         const float* __restrict__ wsum,
                         const float* __restrict__ wfront,
                         const float* __restrict__ wback) {
    int bid = blockIdx.x;
    int tid = threadIdx.x;
    if (bid < DS_BLOCKS) {
        int i = bid*256 + tid;
        int bc = i / (HW/4);
        int r  = i - bc*(HW/4);
        const float4* p = reinterpret_cast<const float4*>(x) + (size_t)bc*DD*(HW/4) + r;
        float4 acc = p[0];
        #pragma unroll
        for (int z = 1; z < DD; z++) {
            float4 v = p[(size_t)z*(HW/4)];
            acc.x += v.x; acc.y += v.y; acc.z += v.z; acc.w += v.w;
        }
        reinterpret_cast<float4*>(g_s)[(size_t)bc*(HW/4) + r] = acc;
    } else {
        int idx = (bid - DS_BLOCKS)*256 + tid;
        if (idx < 3*3*48*64) {
            int co   = idx & 63;
            int rest = idx >> 6;
            int ci   = rest % 48;
            int rest2 = rest / 48;
            int kw = rest2 % 3;
            int kh = rest2 / 3;
            int grp = ci >> 4, ch = ci & 15;
            const float* src = grp==0 ? wsum : (grp==1 ? wfront : wback);
            float v = src[(co*CIN + ch)*9 + kh*3 + kw];
            if (grp) v = -v;
            float hi = to_tf32(v);
            g_wbh[idx] = hi;
            g_wbl[idx] = to_tf32(v - hi);
        }
    }
}

// ============================================================
// Kernel B: 3xTF32 mma.sync implicit conv + softmax + tanh
//   CTA = image row (b,h): M=128 px, N=64 co. 256 threads, 8 warps.
//   Warp wid: mg = wid&3 (px 32*mg..+32), half = wid>>2 (ci half).
//   smem (floats):
//     [0,64)            bias
//     [64, +3*3456)     B hi: [kw3][ci48][co64] pitch 72   (conflict-free)
//     [10432, +3*3456)  B lo
//     [20800, +6760)    patch hi: [col 130][ci 48] pitch 52 (per kh)
//     [27560, +6760)    patch lo
//     [20800, +17408)   logits (2 planes 128x68) -- aliases patch after MMAs
// ============================================================
#define AP 52
#define BP 72
#define SB_KW (48*BP)             // 3456
#define OFF_BH 64
#define OFF_BL (64 + 3*SB_KW)     // 10432
#define OFF_PH (OFF_BL + 3*SB_KW) // 20800
#define OFF_PL (OFF_PH + 130*AP)  // 27560
#define LP 68
#define SMEM_FLOATS (OFF_PH + 2*128*LP)   // 38208
#define SMEM_BYTES (SMEM_FLOATS*4)        // 152832

__global__ void __launch_bounds__(256, 1)
conv_mma(const float* __restrict__ x,
         const float* __restrict__ bias,
         float* __restrict__ out) {
    extern __shared__ float sm[];
    float* sbias = sm;
    float* sBh   = sm + OFF_BH;
    float* sBl   = sm + OFF_BL;
    float* pH    = sm + OFF_PH;
    float* pL    = sm + OFF_PL;
    float* LG    = sm + OFF_PH;      // logits alias

    const int tid = threadIdx.x;
    const int h = blockIdx.x;
    const int b = blockIdx.y;

    if (tid < 64) sbias[tid] = bias[tid];

    const int lane = tid & 31, wid = tid >> 5;
    const int g = lane >> 2, c = lane & 3;
    const int mg = wid & 3, half = wid >> 2;

    float C[2][8][4];
    #pragma unroll
    for (int t = 0; t < 2; t++)
        #pragma unroll
        for (int nt = 0; nt < 8; nt++)
            #pragma unroll
            for (int r = 0; r < 4; r++) C[t][nt][r] = 0.0f;

    for (int kh = 0; kh < 3; kh++) {
        const int row = h + kh - 1;
        const bool valid = (unsigned)row < HH;

        // ---- build A patch (hi/lo) ----
        const float* ps = g_s + (size_t)b*CIN*HW + (size_t)row*WW;
        const float* pf = x  + (size_t)b*CIN*DD*HW + (size_t)row*WW;
        for (int i = tid; i < 48*130; i += 256) {
            int ci = i / 130, r = i - ci*130;
            int col = r - 1;
            float v = 0.0f;
            if (valid && (unsigned)col < WW) {
                int grp = ci >> 4, ch = ci & 15;
                const float* src = (grp == 0) ? ps + (size_t)ch*HW
                                 : pf + ((size_t)ch*DD + (grp == 1 ? 0 : DD-1))*HW;
                v = __ldg(src + col);
            }
            float hi = to_tf32(v);
            pH[r*AP + ci] = hi;
            pL[r*AP + ci] = to_tf32(v - hi);
        }
        // ---- stage B (hi/lo) ----
        for (int i = tid; i < 3*48*64; i += 256) {
            int co = i & 63;
            int rest = i >> 6;
            int ci = rest % 48;
            int kw = rest / 48;
            int d = kw*SB_KW + ci*BP + co;
            int s = ((kh*3 + kw)*48 + ci)*64 + co;
            sBh[d] = __ldg(g_wbh + s);
            sBl[d] = __ldg(g_wbl + s);
        }
        __syncthreads();

        // ---- MMA: 3 precision passes x 3 kw x 3 ksteps (this warp's ci half) ----
        const uint32_t* uPH = reinterpret_cast<const uint32_t*>(pH);
        const uint32_t* uPL = reinterpret_cast<const uint32_t*>(pL);
        const uint32_t* uBh = reinterpret_cast<const uint32_t*>(sBh);
        const uint32_t* uBl = reinterpret_cast<const uint32_t*>(sBl);
        #pragma unroll
        for (int pass = 0; pass < 3; pass++) {
            const uint32_t* A  = (pass == 2) ? uPL : uPH;
            const uint32_t* Bm = (pass == 1) ? uBl : uBh;
            #pragma unroll
            for (int kw = 0; kw < 3; kw++) {
                #pragma unroll
                for (int ks = 0; ks < 3; ks++) {
                    const int k0 = half*24 + ks*8;
                    const uint32_t* ap = A + (mg*32 + kw + g)*AP + k0 + c;
                    const uint32_t* bp = Bm + kw*SB_KW + (k0 + c)*BP + g;
                    uint32_t a0 = ap[0],      a1 = ap[8*AP],      a2 = ap[4],       a3 = ap[8*AP+4];
                    uint32_t a4 = ap[16*AP],  a5 = ap[24*AP],     a6 = ap[16*AP+4], a7 = ap[24*AP+4];
                    uint32_t bb[8][2];
                    #pragma unroll
                    for (int nt = 0; nt < 8; nt++) {
                        bb[nt][0] = bp[nt*8];
                        bb[nt][1] = bp[4*BP + nt*8];
                    }
                    #pragma unroll
                    for (int nt = 0; nt < 8; nt++) {
                        mma8(C[0][nt][0], C[0][nt][1], C[0][nt][2], C[0][nt][3],
                             a0, a1, a2, a3, bb[nt][0], bb[nt][1]);
                        mma8(C[1][nt][0], C[1][nt][1], C[1][nt][2], C[1][nt][3],
                             a4, a5, a6, a7, bb[nt][0], bb[nt][1]);
                    }
                }
            }
        }
        __syncthreads();
    }

    // ---- write partial logits (two planes, one per ci-half group) ----
    float* Lmine = LG + half*(128*LP);
    #pragma unroll
    for (int t = 0; t < 2; t++) {
        int px0 = mg*32 + t*16 + g;
        #pragma unroll
        for (int nt = 0; nt < 8; nt++) {
            int colb = nt*8 + 2*c;
            *reinterpret_cast<float2*>(Lmine + px0*LP + colb)     = make_float2(C[t][nt][0], C[t][nt][1]);
            *reinterpret_cast<float2*>(Lmine + (px0+8)*LP + colb) = make_float2(C[t][nt][2], C[t][nt][3]);
        }
    }
    __syncthreads();

    // ---- softmax + tanh: 2 threads/pixel, shfl combine ----
    const int px = tid >> 1;
    const int hf = tid & 1;
    const float* l0 = LG + px*LP + (hf << 5);
    const float* l1 = l0 + 128*LP;
    const float* mb = sbias + (hf << 5);

    float ev[32];
    float mx = -3.4e38f;
    #pragma unroll
    for (int i = 0; i < 32; i++) {
        float v = l0[i] + l1[i] + mb[i];
        ev[i] = v;
        mx = fmaxf(mx, v);
    }
    mx = fmaxf(mx, __shfl_xor_sync(0xFFFFFFFFu, mx, 1));
    float s = 0.0f;
    #pragma unroll
    for (int i = 0; i < 32; i++) {
        float e = __expf(ev[i] - mx);
        ev[i] = e;
        s += e;
    }
    s += __shfl_xor_sync(0xFFFFFFFFu, s, 1);
    float inv = __fdividef(1.0f, s);

    float* ob = out + (size_t)b*COUT*HW + (size_t)h*WW + px + (size_t)(hf << 5)*HW;
    #pragma unroll
    for (int i = 0; i < 32; i++) {
        float p = ev[i] * inv;
        float t = __expf(-2.0f * p);
        ob[(size_t)i*HW] = __fdividef(1.0f - t, 1.0f + t);
    }
}

// ============================================================
extern "C" void kernel_launch(void* const* d_in, const int* in_sizes, int n_in,
                              void* d_out, int out_size) {
    const float* x      = (const float*)d_in[0];
    const float* wsum   = (const float*)d_in[1];
    const float* wfront = (const float*)d_in[2];
    const float* wback  = (const float*)d_in[3];
    const float* bias   = (const float*)d_in[4];
    float* out = (float*)d_out;

    cudaFuncSetAttribute(conv_mma, cudaFuncAttributeMaxDynamicSharedMemorySize, SMEM_BYTES);

    prep_all<<<DS_BLOCKS + (3*3*48*64 + 255)/256, 256>>>(x, wsum, wfront, wback);
    dim3 grid(HH, B);
    conv_mma<<<grid, 256, SMEM_BYTES>>>(x, bias, out);
}

// round 7
// speedup vs baseline: 1.5732x; 1.5732x over previous
#include <cuda_runtime.h>
#include <cstdint>

#define B 16
#define CIN 16
#define DD 16
#define HH 128
#define WW 128
#define COUT 64
#define HW (HH*WW)

// ---- device scratch ----
__device__ float g_s[B*CIN*HW];          // depth-summed x
__device__ float g_wbh[3*3*48*64];       // weights tf32-hi [kh][kw][ci][co], sign folded
__device__ float g_wbl[3*3*48*64];       // tf32 lo residuals

__device__ __forceinline__ float to_tf32(float v){
    float h; asm("cvt.rna.tf32.f32 %0, %1;" : "=f"(h) : "f"(v)); return h;
}

// m16n8k8 row.col tf32 MMA, accumulate in place
__device__ __forceinline__ void mma8(float* d,
                                     uint32_t a0, uint32_t a1, uint32_t a2, uint32_t a3,
                                     uint32_t b0, uint32_t b1){
    asm volatile("mma.sync.aligned.m16n8k8.row.col.f32.tf32.tf32.f32 "
        "{%0,%1,%2,%3},{%4,%5,%6,%7},{%8,%9},{%0,%1,%2,%3};"
        : "+f"(d[0]), "+f"(d[1]), "+f"(d[2]), "+f"(d[3])
        : "r"(a0), "r"(a1), "r"(a2), "r"(a3), "r"(b0), "r"(b1));
}

// ============================================================
// Kernel A: depth sum + weight hi/lo prep (merged)
// ============================================================
#define DS_BLOCKS (B*CIN*(HW/4)/256)      // 8192
__global__ void prep_all(const float* __restrict__ x,
                         const float* __restrict__ wsum,
                         const float* __restrict__ wfront,
                         const float* __restrict__ wback) {
    int bid = blockIdx.x;
    int tid = threadIdx.x;
    if (bid < DS_BLOCKS) {
        int i = bid*256 + tid;
        int bc = i / (HW/4);
        int r  = i - bc*(HW/4);
        const float4* p = reinterpret_cast<const float4*>(x) + (size_t)bc*DD*(HW/4) + r;
        float4 acc = p[0];
        #pragma unroll
        for (int z = 1; z < DD; z++) {
            float4 v = p[(size_t)z*(HW/4)];
            acc.x += v.x; acc.y += v.y; acc.z += v.z; acc.w += v.w;
        }
        reinterpret_cast<float4*>(g_s)[(size_t)bc*(HW/4) + r] = acc;
    } else {
        int idx = (bid - DS_BLOCKS)*256 + tid;
        if (idx < 3*3*48*64) {
            int co   = idx & 63;
            int rest = idx >> 6;
            int ci   = rest % 48;
            int rest2 = rest / 48;
            int kw = rest2 % 3;
            int kh = rest2 / 3;
            int grp = ci >> 4, ch = ci & 15;
            const float* src = grp==0 ? wsum : (grp==1 ? wfront : wback);
            float v = src[(co*CIN + ch)*9 + kh*3 + kw];
            if (grp) v = -v;
            float hi = to_tf32(v);
            g_wbh[idx] = hi;
            g_wbl[idx] = to_tf32(v - hi);
        }
    }
}

// ============================================================
// Kernel B: 3xTF32 mma.sync implicit conv + softmax + tanh
//   CTA = image row (b,h): M=128 px, N=64 co. 256 threads, 8 warps.
//   Warp tile M32 x N32: wid -> mg = wid&3 (px 32*mg..+32), nh = wid>>2
//   (co half). Full K=48 per warp; C = 32 regs. 2 CTAs/SM.
//   smem (floats):
//     [0,64)            bias
//     [64, +10368)      B hi: [kw3][ci48][co64] pitch 72 (conflict-free)
//     [10432, +10368)   B lo
//     [20800, +6760)    patch v: [col 130][ci 48] pitch 52 (per kh)
//     logits alias B region after last MMA: [px128][co] pitch 68
// ============================================================
#define AP 52
#define BP 72
#define SB_KW (48*BP)             // 3456
#define OFF_BH 64
#define OFF_BL (64 + 3*SB_KW)     // 10432
#define OFF_PV (OFF_BL + 3*SB_KW) // 20800
#define LP 68
#define SMEM_FLOATS (OFF_PV + 130*AP)     // 27560
#define SMEM_BYTES (SMEM_FLOATS*4)        // 110240

__global__ void __launch_bounds__(256, 2)
conv_mma(const float* __restrict__ x,
         const float* __restrict__ bias,
         float* __restrict__ out) {
    extern __shared__ float sm[];
    float* sbias = sm;
    float* sBh   = sm + OFF_BH;
    float* sBl   = sm + OFF_BL;
    float* pV    = sm + OFF_PV;
    float* LG    = sm + OFF_BH;      // logits alias (B region dead after MMAs)

    const int tid = threadIdx.x;
    const int h = blockIdx.x;
    const int b = blockIdx.y;

    if (tid < 64) sbias[tid] = bias[tid];

    const int lane = tid & 31, wid = tid >> 5;
    const int g = lane >> 2, c = lane & 3;
    const int mg = wid & 3, nh = wid >> 2;

    float C[2][4][4];
    #pragma unroll
    for (int m = 0; m < 2; m++)
        #pragma unroll
        for (int nt = 0; nt < 4; nt++)
            #pragma unroll
            for (int r = 0; r < 4; r++) C[m][nt][r] = 0.0f;

    for (int kh = 0; kh < 3; kh++) {
        const int row = h + kh - 1;
        const bool valid = (unsigned)row < HH;

        // ---- build A patch (raw fp32) ----
        const float* ps = g_s + (size_t)b*CIN*HW + (size_t)row*WW;
        const float* pf = x  + (size_t)b*CIN*DD*HW + (size_t)row*WW;
        for (int i = tid; i < 48*130; i += 256) {
            int ci = i / 130, r = i - ci*130;
            int col = r - 1;
            float v = 0.0f;
            if (valid && (unsigned)col < WW) {
                int grp = ci >> 4, ch = ci & 15;
                const float* src = (grp == 0) ? ps + (size_t)ch*HW
                                 : pf + ((size_t)ch*DD + (grp == 1 ? 0 : DD-1))*HW;
                v = __ldg(src + col);
            }
            pV[r*AP + ci] = v;
        }
        // ---- stage B (hi/lo) ----
        for (int i = tid; i < 3*48*64; i += 256) {
            int co = i & 63;
            int rest = i >> 6;
            int ci = rest % 48;
            int kw = rest / 48;
            int d = kw*SB_KW + ci*BP + co;
            int s = ((kh*3 + kw)*48 + ci)*64 + co;
            sBh[d] = __ldg(g_wbh + s);
            sBl[d] = __ldg(g_wbl + s);
        }
        __syncthreads();

        const uint32_t* uBh = reinterpret_cast<const uint32_t*>(sBh);
        const uint32_t* uBl = reinterpret_cast<const uint32_t*>(sBl);
        #pragma unroll
        for (int kw = 0; kw < 3; kw++) {
            const float* apb = pV + (mg*32 + kw + g)*AP + c;
            #pragma unroll 2
            for (int ks = 0; ks < 6; ks++) {
                const int k0 = ks*8;
                // A fragments: rows g,g+8,g+16,g+24; cols k0+c, k0+c+4
                float v0 = apb[k0],         v1 = apb[k0 + 8*AP];
                float v2 = apb[k0 + 4],     v3 = apb[k0 + 8*AP + 4];
                float v4 = apb[k0 + 16*AP], v5 = apb[k0 + 24*AP];
                float v6 = apb[k0 + 16*AP + 4], v7 = apb[k0 + 24*AP + 4];
                uint32_t h0 = __float_as_uint(to_tf32(v0));
                uint32_t h1 = __float_as_uint(to_tf32(v1));
                uint32_t h2 = __float_as_uint(to_tf32(v2));
                uint32_t h3 = __float_as_uint(to_tf32(v3));
                uint32_t h4 = __float_as_uint(to_tf32(v4));
                uint32_t h5 = __float_as_uint(to_tf32(v5));
                uint32_t h6 = __float_as_uint(to_tf32(v6));
                uint32_t h7 = __float_as_uint(to_tf32(v7));
                uint32_t l0 = __float_as_uint(to_tf32(v0 - __uint_as_float(h0)));
                uint32_t l1 = __float_as_uint(to_tf32(v1 - __uint_as_float(h1)));
                uint32_t l2 = __float_as_uint(to_tf32(v2 - __uint_as_float(h2)));
                uint32_t l3 = __float_as_uint(to_tf32(v3 - __uint_as_float(h3)));
                uint32_t l4 = __float_as_uint(to_tf32(v4 - __uint_as_float(h4)));
                uint32_t l5 = __float_as_uint(to_tf32(v5 - __uint_as_float(h5)));
                uint32_t l6 = __float_as_uint(to_tf32(v6 - __uint_as_float(h6)));
                uint32_t l7 = __float_as_uint(to_tf32(v7 - __uint_as_float(h7)));

                const int bbase = kw*SB_KW + (k0 + c)*BP + nh*32 + g;
                uint32_t bh[4][2], bl[4][2];
                #pragma unroll
                for (int nt = 0; nt < 4; nt++) {
                    bh[nt][0] = uBh[bbase + nt*8];
                    bh[nt][1] = uBh[bbase + 4*BP + nt*8];
                    bl[nt][0] = uBl[bbase + nt*8];
                    bl[nt][1] = uBl[bbase + 4*BP + nt*8];
                }
                #pragma unroll
                for (int nt = 0; nt < 4; nt++) {
                    mma8(C[0][nt], h0, h1, h2, h3, bh[nt][0], bh[nt][1]);
                    mma8(C[1][nt], h4, h5, h6, h7, bh[nt][0], bh[nt][1]);
                    mma8(C[0][nt], h0, h1, h2, h3, bl[nt][0], bl[nt][1]);
                    mma8(C[1][nt], h4, h5, h6, h7, bl[nt][0], bl[nt][1]);
                    mma8(C[0][nt], l0, l1, l2, l3, bh[nt][0], bh[nt][1]);
                    mma8(C[1][nt], l4, l5, l6, l7, bh[nt][0], bh[nt][1]);
                }
            }
        }
        __syncthreads();
    }

    // ---- write logits (single plane; each output owned by one warp) ----
    #pragma unroll
    for (int m = 0; m < 2; m++) {
        int px0 = mg*32 + m*16 + g;
        #pragma unroll
        for (int nt = 0; nt < 4; nt++) {
            int colb = nh*32 + nt*8 + 2*c;
            *reinterpret_cast<float2*>(LG + px0*LP + colb)     = make_float2(C[m][nt][0], C[m][nt][1]);
            *reinterpret_cast<float2*>(LG + (px0+8)*LP + colb) = make_float2(C[m][nt][2], C[m][nt][3]);
        }
    }
    __syncthreads();

    // ---- softmax + tanh: 2 threads/pixel, shfl combine ----
    const int px = tid >> 1;
    const int hf = tid & 1;
    const float* l0p = LG + px*LP + (hf << 5);
    const float* mb  = sbias + (hf << 5);

    float ev[32];
    float mx = -3.4e38f;
    #pragma unroll
    for (int i = 0; i < 32; i++) {
        float v = l0p[i] + mb[i];
        ev[i] = v;
        mx = fmaxf(mx, v);
    }
    mx = fmaxf(mx, __shfl_xor_sync(0xFFFFFFFFu, mx, 1));
    float s = 0.0f;
    #pragma unroll
    for (int i = 0; i < 32; i++) {
        float e = __expf(ev[i] - mx);
        ev[i] = e;
        s += e;
    }
    s += __shfl_xor_sync(0xFFFFFFFFu, s, 1);
    float inv = __fdividef(1.0f, s);

    float* ob = out + (size_t)b*COUT*HW + (size_t)h*WW + px + (size_t)(hf << 5)*HW;
    #pragma unroll
    for (int i = 0; i < 32; i++) {
        float p = ev[i] * inv;
        float t = __expf(-2.0f * p);
        ob[(size_t)i*HW] = __fdividef(1.0f - t, 1.0f + t);
    }
}

// ============================================================
extern "C" void kernel_launch(void* const* d_in, const int* in_sizes, int n_in,
                              void* d_out, int out_size) {
    const float* x      = (const float*)d_in[0];
    const float* wsum   = (const float*)d_in[1];
    const float* wfront = (const float*)d_in[2];
    const float* wback  = (const float*)d_in[3];
    const float* bias   = (const float*)d_in[4];
    float* out = (float*)d_out;

    cudaFuncSetAttribute(conv_mma, cudaFuncAttributeMaxDynamicSharedMemorySize, SMEM_BYTES);

    prep_all<<<DS_BLOCKS + (3*3*48*64 + 255)/256, 256>>>(x, wsum, wfront, wback);
    dim3 grid(HH, B);
    conv_mma<<<grid, 256, SMEM_BYTES>>>(x, bias, out);
}

// round 9
// speedup vs baseline: 1.7018x; 1.0817x over previous
#include <cuda_runtime.h>
#include <cstdint>

#define B 16
#define CIN 16
#define DD 16
#define HH 128
#define WW 128
#define COUT 64
#define HW (HH*WW)

// ---- device scratch ----
__device__ float g_s[B*CIN*HW];          // depth-summed x
__device__ float2 g_wb2[3*3*48*64];      // weights (tf32-hi, lo) [kh][kw][ci][co], sign folded

#define TF32_MASK 0xFFFFE000u

__device__ __forceinline__ float to_tf32(float v){
    float h; asm("cvt.rna.tf32.f32 %0, %1;" : "=f"(h) : "f"(v)); return h;
}

// m16n8k8 row.col tf32 MMA, accumulate in place (operands as b32 tf32 containers)
__device__ __forceinline__ void mma8(float* d,
                                     uint32_t a0, uint32_t a1, uint32_t a2, uint32_t a3,
                                     uint32_t b0, uint32_t b1){
    asm volatile("mma.sync.aligned.m16n8k8.row.col.f32.tf32.tf32.f32 "
        "{%0,%1,%2,%3},{%4,%5,%6,%7},{%8,%9},{%0,%1,%2,%3};"
        : "+f"(d[0]), "+f"(d[1]), "+f"(d[2]), "+f"(d[3])
        : "r"(a0), "r"(a1), "r"(a2), "r"(a3), "r"(b0), "r"(b1));
}

// ============================================================
// Kernel A: depth sum + weight hi/lo prep (merged)
// ============================================================
#define DS_BLOCKS (B*CIN*(HW/4)/256)      // 8192
__global__ void prep_all(const float* __restrict__ x,
                         const float* __restrict__ wsum,
                         const float* __restrict__ wfront,
                         const float* __restrict__ wback) {
    int bid = blockIdx.x;
    int tid = threadIdx.x;
    if (bid < DS_BLOCKS) {
        int i = bid*256 + tid;
        int bc = i / (HW/4);
        int r  = i - bc*(HW/4);
        const float4* p = reinterpret_cast<const float4*>(x) + (size_t)bc*DD*(HW/4) + r;
        float4 acc = p[0];
        #pragma unroll
        for (int z = 1; z < DD; z++) {
            float4 v = p[(size_t)z*(HW/4)];
            acc.x += v.x; acc.y += v.y; acc.z += v.z; acc.w += v.w;
        }
        reinterpret_cast<float4*>(g_s)[(size_t)bc*(HW/4) + r] = acc;
    } else {
        int idx = (bid - DS_BLOCKS)*256 + tid;
        if (idx < 3*3*48*64) {
            int co   = idx & 63;
            int rest = idx >> 6;
            int ci   = rest % 48;
            int rest2 = rest / 48;
            int kw = rest2 % 3;
            int kh = rest2 / 3;
            int grp = ci >> 4, ch = ci & 15;
            const float* src = grp==0 ? wsum : (grp==1 ? wfront : wback);
            float v = src[(co*CIN + ch)*9 + kh*3 + kw];
            if (grp) v = -v;
            float hi = to_tf32(v);   // rna hi for weights (done once; slightly better than trunc)
            g_wb2[idx] = make_float2(hi, v - hi);
        }
    }
}

// ============================================================
// Kernel B: 3xTF32 mma.sync implicit conv + softmax + tanh
//   CTA = image row (b,h): M=128 px, N=64 co. 256 threads, 8 warps, 2 CTAs/SM.
//   Warp tile M32 x N32: mg = wid&3, nh = wid>>2.
//   A hi/lo split in registers via tf32 truncation mask (no CVTs in hot loop).
//   B staged as float2(hi,lo), pitch 68 f2 -> fragment pair = one LDS.64,
//   conflict-free ((4c+g) mod 16 permutation per phase).
//   smem (floats):
//     [0,64)           bias
//     [64, +19584)     B2: [kw3][ci48][co64] float2, pitch 68 f2
//     [19648, +6760)   patch v: [col130][ci48] pitch 52
//     logits alias B2 region after MMAs: [px128][co] pitch 68
// ============================================================
#define AP 52
#define BP2 68
#define SB2_KW (48*BP2)            // 3264 float2
#define OFF_B2 64                  // float offset (8B aligned: 256B)
#define OFF_PV (OFF_B2 + 3*SB2_KW*2)   // 64 + 19584 = 19648
#define LP 68
#define SMEM_FLOATS (OFF_PV + 130*AP)  // 26408
#define SMEM_BYTES (SMEM_FLOATS*4)     // 105632

__global__ void __launch_bounds__(256, 2)
conv_mma(const float* __restrict__ x,
         const float* __restrict__ bias,
         float* __restrict__ out) {
    extern __shared__ float sm[];
    float* sbias = sm;
    float2* sB2  = reinterpret_cast<float2*>(sm + OFF_B2);
    float* pV    = sm + OFF_PV;
    float* LG    = sm + OFF_B2;      // logits alias (B region dead after MMAs)

    const int tid = threadIdx.x;
    const int h = blockIdx.x;
    const int b = blockIdx.y;

    if (tid < 64) sbias[tid] = bias[tid];

    const int lane = tid & 31, wid = tid >> 5;
    const int g = lane >> 2, c = lane & 3;
    const int mg = wid & 3, nh = wid >> 2;

    float C[2][4][4];
    #pragma unroll
    for (int m = 0; m < 2; m++)
        #pragma unroll
        for (int nt = 0; nt < 4; nt++)
            #pragma unroll
            for (int r = 0; r < 4; r++) C[m][nt][r] = 0.0f;

    for (int kh = 0; kh < 3; kh++) {
        const int row = h + kh - 1;
        const bool valid = (unsigned)row < HH;

        // ---- build A patch (raw fp32) ----
        const float* ps = g_s + (size_t)b*CIN*HW + (size_t)row*WW;
        const float* pf = x  + (size_t)b*CIN*DD*HW + (size_t)row*WW;
        for (int i = tid; i < 48*130; i += 256) {
            int ci = i / 130, r = i - ci*130;
            int col = r - 1;
            float v = 0.0f;
            if (valid && (unsigned)col < WW) {
                int grp = ci >> 4, ch = ci & 15;
                const float* src = (grp == 0) ? ps + (size_t)ch*HW
                                 : pf + ((size_t)ch*DD + (grp == 1 ? 0 : DD-1))*HW;
                v = __ldg(src + col);
            }
            pV[r*AP + ci] = v;
        }
        // ---- stage B2 (hi,lo interleaved) ----
        {
            const float2* srcw = g_wb2 + (size_t)kh*3*48*64;
            for (int i = tid; i < 3*48*64; i += 256) {
                int co = i & 63;
                int rest = i >> 6;
                int ci = rest % 48;
                int kw = rest / 48;
                sB2[kw*SB2_KW + ci*BP2 + co] = __ldg(srcw + i);
            }
        }
        __syncthreads();

        #pragma unroll
        for (int kw = 0; kw < 3; kw++) {
            const float* apb = pV + (mg*32 + kw + g)*AP + c;
            const float2* bkw = sB2 + kw*SB2_KW + nh*32 + g;
            #pragma unroll 2
            for (int ks = 0; ks < 6; ks++) {
                const int k0 = ks*8;
                // A fragments: rows g,g+8,g+16,g+24; cols k0+c, k0+c+4
                float v0 = apb[k0],             v1 = apb[k0 + 8*AP];
                float v2 = apb[k0 + 4],         v3 = apb[k0 + 8*AP + 4];
                float v4 = apb[k0 + 16*AP],     v5 = apb[k0 + 24*AP];
                float v6 = apb[k0 + 16*AP + 4], v7 = apb[k0 + 24*AP + 4];
                uint32_t h0 = __float_as_uint(v0) & TF32_MASK;
                uint32_t h1 = __float_as_uint(v1) & TF32_MASK;
                uint32_t h2 = __float_as_uint(v2) & TF32_MASK;
                uint32_t h3 = __float_as_uint(v3) & TF32_MASK;
                uint32_t h4 = __float_as_uint(v4) & TF32_MASK;
                uint32_t h5 = __float_as_uint(v5) & TF32_MASK;
                uint32_t h6 = __float_as_uint(v6) & TF32_MASK;
                uint32_t h7 = __float_as_uint(v7) & TF32_MASK;
                uint32_t l0 = __float_as_uint(v0 - __uint_as_float(h0));
                uint32_t l1 = __float_as_uint(v1 - __uint_as_float(h1));
                uint32_t l2 = __float_as_uint(v2 - __uint_as_float(h2));
                uint32_t l3 = __float_as_uint(v3 - __uint_as_float(h3));
                uint32_t l4 = __float_as_uint(v4 - __uint_as_float(h4));
                uint32_t l5 = __float_as_uint(v5 - __uint_as_float(h5));
                uint32_t l6 = __float_as_uint(v6 - __uint_as_float(h6));
                uint32_t l7 = __float_as_uint(v7 - __uint_as_float(h7));

                const float2* bp2 = bkw + (k0 + c)*BP2;
                float2 q0[4], q1[4];
                #pragma unroll
                for (int nt = 0; nt < 4; nt++) {
                    q0[nt] = bp2[nt*8];            // (Bhi, Blo) at ci=k0+c
                    q1[nt] = bp2[4*BP2 + nt*8];    // (Bhi, Blo) at ci=k0+c+4
                }
                #pragma unroll
                for (int nt = 0; nt < 4; nt++) {
                    uint32_t bh0 = __float_as_uint(q0[nt].x), bh1 = __float_as_uint(q1[nt].x);
                    uint32_t bl0 = __float_as_uint(q0[nt].y), bl1 = __float_as_uint(q1[nt].y);
                    mma8(C[0][nt], h0, h1, h2, h3, bh0, bh1);
                    mma8(C[1][nt], h4, h5, h6, h7, bh0, bh1);
                    mma8(C[0][nt], h0, h1, h2, h3, bl0, bl1);
                    mma8(C[1][nt], h4, h5, h6, h7, bl0, bl1);
                    mma8(C[0][nt], l0, l1, l2, l3, bh0, bh1);
                    mma8(C[1][nt], l4, l5, l6, l7, bh0, bh1);
                }
            }
        }
        __syncthreads();
    }

    // ---- write logits (single plane; each output owned by one warp) ----
    #pragma unroll
    for (int m = 0; m < 2; m++) {
        int px0 = mg*32 + m*16 + g;
        #pragma unroll
        for (int nt = 0; nt < 4; nt++) {
            int colb = nh*32 + nt*8 + 2*c;
            *reinterpret_cast<float2*>(LG + px0*LP + colb)     = make_float2(C[m][nt][0], C[m][nt][1]);
            *reinterpret_cast<float2*>(LG + (px0+8)*LP + colb) = make_float2(C[m][nt][2], C[m][nt][3]);
        }
    }
    __syncthreads();

    // ---- softmax + tanh: 2 threads/pixel, shfl combine ----
    const int px = tid >> 1;
    const int hf = tid & 1;
    const float* l0p = LG + px*LP + (hf << 5);
    const float* mb  = sbias + (hf << 5);

    float ev[32];
    float mx = -3.4e38f;
    #pragma unroll
    for (int i = 0; i < 32; i++) {
        float v = l0p[i] + mb[i];
        ev[i] = v;
        mx = fmaxf(mx, v);
    }
    mx = fmaxf(mx, __shfl_xor_sync(0xFFFFFFFFu, mx, 1));
    float s = 0.0f;
    #pragma unroll
    for (int i = 0; i < 32; i++) {
        float e = __expf(ev[i] - mx);
        ev[i] = e;
        s += e;
    }
    s += __shfl_xor_sync(0xFFFFFFFFu, s, 1);
    float inv = __fdividef(1.0f, s);

    float* ob = out + (size_t)b*COUT*HW + (size_t)h*WW + px + (size_t)(hf << 5)*HW;
    #pragma unroll
    for (int i = 0; i < 32; i++) {
        float p = ev[i] * inv;
        float t = __expf(-2.0f * p);
        ob[(size_t)i*HW] = __fdividef(1.0f - t, 1.0f + t);
    }
}

// ============================================================
extern "C" void kernel_launch(void* const* d_in, const int* in_sizes, int n_in,
                              void* d_out, int out_size) {
    const float* x      = (const float*)d_in[0];
    const float* wsum   = (const float*)d_in[1];
    const float* wfront = (const float*)d_in[2];
    const float* wback  = (const float*)d_in[3];
    const float* bias   = (const float*)d_in[4];
    float* out = (float*)d_out;

    cudaFuncSetAttribute(conv_mma, cudaFuncAttributeMaxDynamicSharedMemorySize, SMEM_BYTES);

    prep_all<<<DS_BLOCKS + (3*3*48*64 + 255)/256, 256>>>(x, wsum, wfront, wback);
    dim3 grid(HH, B);
    conv_mma<<<grid, 256, SMEM_BYTES>>>(x, bias, out);
}

// round 10
// speedup vs baseline: 1.9966x; 1.1732x over previous
#include <cuda_runtime.h>
#include <cstdint>

#define B 16
#define CIN 16
#define DD 16
#define HH 128
#define WW 128
#define COUT 64
#define HW (HH*WW)

// ---- device scratch ----
__device__ float g_s[B*CIN*HW];          // depth-summed x
__device__ float g_w[3*3*48*64];         // folded fp32 weights [kh][kw][ci][co]

#define TF32_MASK 0xFFFFE000u

// m16n8k8 row.col tf32 MMA, accumulate in place (operands as b32 tf32 containers)
__device__ __forceinline__ void mma8(float* d,
                                     uint32_t a0, uint32_t a1, uint32_t a2, uint32_t a3,
                                     uint32_t b0, uint32_t b1){
    asm volatile("mma.sync.aligned.m16n8k8.row.col.f32.tf32.tf32.f32 "
        "{%0,%1,%2,%3},{%4,%5,%6,%7},{%8,%9},{%0,%1,%2,%3};"
        : "+f"(d[0]), "+f"(d[1]), "+f"(d[2]), "+f"(d[3])
        : "r"(a0), "r"(a1), "r"(a2), "r"(a3), "r"(b0), "r"(b1));
}

// ============================================================
// Kernel A: depth sum + weight prep (merged)
// ============================================================
#define DS_BLOCKS (B*CIN*(HW/4)/256)      // 8192
__global__ void prep_all(const float* __restrict__ x,
                         const float* __restrict__ wsum,
                         const float* __restrict__ wfront,
                         const float* __restrict__ wback) {
    int bid = blockIdx.x;
    int tid = threadIdx.x;
    if (bid < DS_BLOCKS) {
        int i = bid*256 + tid;
        int bc = i / (HW/4);
        int r  = i - bc*(HW/4);
        const float4* p = reinterpret_cast<const float4*>(x) + (size_t)bc*DD*(HW/4) + r;
        float4 acc = p[0];
        #pragma unroll
        for (int z = 1; z < DD; z++) {
            float4 v = p[(size_t)z*(HW/4)];
            acc.x += v.x; acc.y += v.y; acc.z += v.z; acc.w += v.w;
        }
        reinterpret_cast<float4*>(g_s)[(size_t)bc*(HW/4) + r] = acc;
    } else {
        int idx = (bid - DS_BLOCKS)*256 + tid;
        if (idx < 3*3*48*64) {
            int co   = idx & 63;
            int rest = idx >> 6;
            int ci   = rest % 48;
            int rest2 = rest / 48;
            int kw = rest2 % 3;
            int kh = rest2 / 3;
            int grp = ci >> 4, ch = ci & 15;
            const float* src = grp==0 ? wsum : (grp==1 ? wfront : wback);
            float v = src[(co*CIN + ch)*9 + kh*3 + kw];
            if (grp) v = -v;
            g_w[idx] = v;
        }
    }
}

// ============================================================
// Kernel B: 3xTF32 mma.sync implicit conv + softmax + tanh
//   CTA = image row (b,h): M=128 px, N=64 co. 256 threads, 8 warps, 3 CTAs/SM.
//   Warp tile M32 x N32: mg = wid&3, nh = wid>>2.
//   BOTH A and B hi/lo split in registers via tf32 trunc mask + exact FADD
//   residual -> B stored raw fp32 in smem (half the bytes, 3 CTAs fit).
//   A pitch 52 (20g+c perm), B pitch 72 (8c+g perm): conflict-free.
//   smem (floats):
//     [0,64)            bias
//     [64, +10368)      B: [kw3][ci48][co64] fp32, pitch 72
//     [10432, +6760)    patch v: [col130][ci48] pitch 52
//     logits alias B region after MMAs: [px128][co] pitch 68 (8704 <= 10368)
// ============================================================
#define AP 52
#define BP 72
#define SB_KW (48*BP)              // 3456
#define OFF_B 64
#define OFF_PV (OFF_B + 3*SB_KW)   // 10432
#define LP 68
#define SMEM_FLOATS (OFF_PV + 130*AP)  // 17192
#define SMEM_BYTES (SMEM_FLOATS*4)     // 68768

__global__ void __launch_bounds__(256, 3)
conv_mma(const float* __restrict__ x,
         const float* __restrict__ bias,
         float* __restrict__ out) {
    extern __shared__ float sm[];
    float* sbias = sm;
    float* sB    = sm + OFF_B;
    float* pV    = sm + OFF_PV;
    float* LG    = sm + OFF_B;       // logits alias (B region dead after MMAs)

    const int tid = threadIdx.x;
    const int h = blockIdx.x;
    const int b = blockIdx.y;

    if (tid < 64) sbias[tid] = bias[tid];

    const int lane = tid & 31, wid = tid >> 5;
    const int g = lane >> 2, c = lane & 3;
    const int mg = wid & 3, nh = wid >> 2;

    float C[2][4][4];
    #pragma unroll
    for (int m = 0; m < 2; m++)
        #pragma unroll
        for (int nt = 0; nt < 4; nt++)
            #pragma unroll
            for (int r = 0; r < 4; r++) C[m][nt][r] = 0.0f;

    for (int kh = 0; kh < 3; kh++) {
        const int row = h + kh - 1;
        const bool valid = (unsigned)row < HH;

        // ---- build A patch (raw fp32) ----
        const float* ps = g_s + (size_t)b*CIN*HW + (size_t)row*WW;
        const float* pf = x  + (size_t)b*CIN*DD*HW + (size_t)row*WW;
        for (int i = tid; i < 48*130; i += 256) {
            int ci = i / 130, r = i - ci*130;
            int col = r - 1;
            float v = 0.0f;
            if (valid && (unsigned)col < WW) {
                int grp = ci >> 4, ch = ci & 15;
                const float* src = (grp == 0) ? ps + (size_t)ch*HW
                                 : pf + ((size_t)ch*DD + (grp == 1 ? 0 : DD-1))*HW;
                v = __ldg(src + col);
            }
            pV[r*AP + ci] = v;
        }
        // ---- stage B raw fp32 ----
        {
            const float* srcw = g_w + (size_t)kh*3*48*64;
            for (int i = tid; i < 3*48*64; i += 256) {
                int co = i & 63;
                int rest = i >> 6;
                int ci = rest % 48;
                int kw = rest / 48;
                sB[kw*SB_KW + ci*BP + co] = __ldg(srcw + i);
            }
        }
        __syncthreads();

        #pragma unroll
        for (int kw = 0; kw < 3; kw++) {
            const float* apb = pV + (mg*32 + kw + g)*AP + c;
            const float* bkw = sB + kw*SB_KW + nh*32 + g;
            #pragma unroll 2
            for (int ks = 0; ks < 6; ks++) {
                const int k0 = ks*8;
                // A fragments: rows g,g+8,g+16,g+24; cols k0+c, k0+c+4
                float v0 = apb[k0],             v1 = apb[k0 + 8*AP];
                float v2 = apb[k0 + 4],         v3 = apb[k0 + 8*AP + 4];
                float v4 = apb[k0 + 16*AP],     v5 = apb[k0 + 24*AP];
                float v6 = apb[k0 + 16*AP + 4], v7 = apb[k0 + 24*AP + 4];
                uint32_t h0 = __float_as_uint(v0) & TF32_MASK;
                uint32_t h1 = __float_as_uint(v1) & TF32_MASK;
                uint32_t h2 = __float_as_uint(v2) & TF32_MASK;
                uint32_t h3 = __float_as_uint(v3) & TF32_MASK;
                uint32_t h4 = __float_as_uint(v4) & TF32_MASK;
                uint32_t h5 = __float_as_uint(v5) & TF32_MASK;
                uint32_t h6 = __float_as_uint(v6) & TF32_MASK;
                uint32_t h7 = __float_as_uint(v7) & TF32_MASK;
                uint32_t l0 = __float_as_uint(v0 - __uint_as_float(h0));
                uint32_t l1 = __float_as_uint(v1 - __uint_as_float(h1));
                uint32_t l2 = __float_as_uint(v2 - __uint_as_float(h2));
                uint32_t l3 = __float_as_uint(v3 - __uint_as_float(h3));
                uint32_t l4 = __float_as_uint(v4 - __uint_as_float(h4));
                uint32_t l5 = __float_as_uint(v5 - __uint_as_float(h5));
                uint32_t l6 = __float_as_uint(v6 - __uint_as_float(h6));
                uint32_t l7 = __float_as_uint(v7 - __uint_as_float(h7));

                const float* bp = bkw + (k0 + c)*BP;
                #pragma unroll
                for (int nt = 0; nt < 4; nt++) {
                    float r0 = bp[nt*8];
                    float r1 = bp[4*BP + nt*8];
                    uint32_t bh0 = __float_as_uint(r0) & TF32_MASK;
                    uint32_t bh1 = __float_as_uint(r1) & TF32_MASK;
                    uint32_t bl0 = __float_as_uint(r0 - __uint_as_float(bh0));
                    uint32_t bl1 = __float_as_uint(r1 - __uint_as_float(bh1));
                    mma8(C[0][nt], h0, h1, h2, h3, bh0, bh1);
                    mma8(C[1][nt], h4, h5, h6, h7, bh0, bh1);
                    mma8(C[0][nt], h0, h1, h2, h3, bl0, bl1);
                    mma8(C[1][nt], h4, h5, h6, h7, bl0, bl1);
                    mma8(C[0][nt], l0, l1, l2, l3, bh0, bh1);
                    mma8(C[1][nt], l4, l5, l6, l7, bh0, bh1);
                }
            }
        }
        __syncthreads();
    }

    // ---- write logits (single plane; each output owned by one warp) ----
    #pragma unroll
    for (int m = 0; m < 2; m++) {
        int px0 = mg*32 + m*16 + g;
        #pragma unroll
        for (int nt = 0; nt < 4; nt++) {
            int colb = nh*32 + nt*8 + 2*c;
            *reinterpret_cast<float2*>(LG + px0*LP + colb)     = make_float2(C[m][nt][0], C[m][nt][1]);
            *reinterpret_cast<float2*>(LG + (px0+8)*LP + colb) = make_float2(C[m][nt][2], C[m][nt][3]);
        }
    }
    __syncthreads();

    // ---- softmax + tanh: 2 threads/pixel, shfl combine ----
    const int px = tid >> 1;
    const int hf = tid & 1;
    const float* l0p = LG + px*LP + (hf << 5);
    const float* mb  = sbias + (hf << 5);

    float ev[32];
    float mx = -3.4e38f;
    #pragma unroll
    for (int i = 0; i < 32; i++) {
        float v = l0p[i] + mb[i];
        ev[i] = v;
        mx = fmaxf(mx, v);
    }
    mx = fmaxf(mx, __shfl_xor_sync(0xFFFFFFFFu, mx, 1));
    float s = 0.0f;
    #pragma unroll
    for (int i = 0; i < 32; i++) {
        float e = __expf(ev[i] - mx);
        ev[i] = e;
        s += e;
    }
    s += __shfl_xor_sync(0xFFFFFFFFu, s, 1);
    float inv = __fdividef(1.0f, s);

    float* ob = out + (size_t)b*COUT*HW + (size_t)h*WW + px + (size_t)(hf << 5)*HW;
    #pragma unroll
    for (int i = 0; i < 32; i++) {
        float p = ev[i] * inv;
        float t = __expf(-2.0f * p);
        ob[(size_t)i*HW] = __fdividef(1.0f - t, 1.0f + t);
    }
}

// ============================================================
extern "C" void kernel_launch(void* const* d_in, const int* in_sizes, int n_in,
                              void* d_out, int out_size) {
    const float* x      = (const float*)d_in[0];
    const float* wsum   = (const float*)d_in[1];
    const float* wfront = (const float*)d_in[2];
    const float* wback  = (const float*)d_in[3];
    const float* bias   = (const float*)d_in[4];
    float* out = (float*)d_out;

    cudaFuncSetAttribute(conv_mma, cudaFuncAttributeMaxDynamicSharedMemorySize, SMEM_BYTES);

    prep_all<<<DS_BLOCKS + (3*3*48*64 + 255)/256, 256>>>(x, wsum, wfront, wback);
    dim3 grid(HH, B);
    conv_mma<<<grid, 256, SMEM_BYTES>>>(x, bias, out);
}

// round 11
// speedup vs baseline: 2.0078x; 1.0056x over previous
#include <cuda_runtime.h>
#include <cstdint>

#define B 16
#define CIN 16
#define DD 16
#define HH 128
#define WW 128
#define COUT 64
#define HW (HH*WW)

// ---- device scratch ----
__device__ float g_s[B*CIN*HW];          // depth-summed x
__device__ float g_w[3*3*48*64];         // folded fp32 weights [kh][kw][ci][co]

#define TF32_MASK 0xFFFFE000u

// m16n8k8 row.col tf32 MMA, accumulate in place.
// NOT volatile: pure register function; lets ptxas schedule/interleave.
__device__ __forceinline__ void mma8(float* d,
                                     uint32_t a0, uint32_t a1, uint32_t a2, uint32_t a3,
                                     uint32_t b0, uint32_t b1){
    asm("mma.sync.aligned.m16n8k8.row.col.f32.tf32.tf32.f32 "
        "{%0,%1,%2,%3},{%4,%5,%6,%7},{%8,%9},{%0,%1,%2,%3};"
        : "+f"(d[0]), "+f"(d[1]), "+f"(d[2]), "+f"(d[3])
        : "r"(a0), "r"(a1), "r"(a2), "r"(a3), "r"(b0), "r"(b1));
}

// ============================================================
// Kernel A: depth sum + weight prep (merged)
// ============================================================
#define DS_BLOCKS (B*CIN*(HW/4)/256)      // 8192
__global__ void prep_all(const float* __restrict__ x,
                         const float* __restrict__ wsum,
                         const float* __restrict__ wfront,
                         const float* __restrict__ wback) {
    int bid = blockIdx.x;
    int tid = threadIdx.x;
    if (bid < DS_BLOCKS) {
        int i = bid*256 + tid;
        int bc = i / (HW/4);
        int r  = i - bc*(HW/4);
        const float4* p = reinterpret_cast<const float4*>(x) + (size_t)bc*DD*(HW/4) + r;
        float4 acc = p[0];
        #pragma unroll
        for (int z = 1; z < DD; z++) {
            float4 v = p[(size_t)z*(HW/4)];
            acc.x += v.x; acc.y += v.y; acc.z += v.z; acc.w += v.w;
        }
        reinterpret_cast<float4*>(g_s)[(size_t)bc*(HW/4) + r] = acc;
    } else {
        int idx = (bid - DS_BLOCKS)*256 + tid;
        if (idx < 3*3*48*64) {
            int co   = idx & 63;
            int rest = idx >> 6;
            int ci   = rest % 48;
            int rest2 = rest / 48;
            int kw = rest2 % 3;
            int kh = rest2 / 3;
            int grp = ci >> 4, ch = ci & 15;
            const float* src = grp==0 ? wsum : (grp==1 ? wfront : wback);
            float v = src[(co*CIN + ch)*9 + kh*3 + kw];
            if (grp) v = -v;
            g_w[idx] = v;
        }
    }
}

// ============================================================
// Kernel B: 3xTF32 mma.sync implicit conv + softmax + tanh
//   CTA = image row (b,h): M=128 px, N=64 co. 256 threads, 8 warps, 3 CTAs/SM.
//   Warp tile M32 x N32: mg = wid&3, nh = wid>>2.
//   A and B hi/lo split in registers (tf32 trunc mask + exact FADD residual).
//   Inner loop is TERM-MAJOR: all 8 MMAs of AhiBhi, then AhiBlo, then AloBhi
//   -> same-accumulator reuse distance 8 (was 2), hides HMMA latency.
//   smem (floats):
//     [0,64)            bias
//     [64, +10368)      B: [kw3][ci48][co64] fp32, pitch 72 (8c+g perm, cf)
//     [10432, +6760)    patch v: [col130][ci48] pitch 52 (20g+c perm, cf)
//     logits alias B region after MMAs: [px128][co] pitch 68
// ============================================================
#define AP 52
#define BP 72
#define SB_KW (48*BP)              // 3456
#define OFF_B 64
#define OFF_PV (OFF_B + 3*SB_KW)   // 10432
#define LP 68
#define SMEM_FLOATS (OFF_PV + 130*AP)  // 17192
#define SMEM_BYTES (SMEM_FLOATS*4)     // 68768

__global__ void __launch_bounds__(256, 3)
conv_mma(const float* __restrict__ x,
         const float* __restrict__ bias,
         float* __restrict__ out) {
    extern __shared__ float sm[];
    float* sbias = sm;
    float* sB    = sm + OFF_B;
    float* pV    = sm + OFF_PV;
    float* LG    = sm + OFF_B;       // logits alias (B region dead after MMAs)

    const int tid = threadIdx.x;
    const int h = blockIdx.x;
    const int b = blockIdx.y;

    if (tid < 64) sbias[tid] = bias[tid];

    const int lane = tid & 31, wid = tid >> 5;
    const int g = lane >> 2, c = lane & 3;
    const int mg = wid & 3, nh = wid >> 2;

    float C[2][4][4];
    #pragma unroll
    for (int m = 0; m < 2; m++)
        #pragma unroll
        for (int nt = 0; nt < 4; nt++)
            #pragma unroll
            for (int r = 0; r < 4; r++) C[m][nt][r] = 0.0f;

    for (int kh = 0; kh < 3; kh++) {
        const int row = h + kh - 1;
        const bool valid = (unsigned)row < HH;

        // ---- build A patch (raw fp32) ----
        const float* ps = g_s + (size_t)b*CIN*HW + (size_t)row*WW;
        const float* pf = x  + (size_t)b*CIN*DD*HW + (size_t)row*WW;
        for (int i = tid; i < 48*130; i += 256) {
            int ci = i / 130, r = i - ci*130;
            int col = r - 1;
            float v = 0.0f;
            if (valid && (unsigned)col < WW) {
                int grp = ci >> 4, ch = ci & 15;
                const float* src = (grp == 0) ? ps + (size_t)ch*HW
                                 : pf + ((size_t)ch*DD + (grp == 1 ? 0 : DD-1))*HW;
                v = __ldg(src + col);
            }
            pV[r*AP + ci] = v;
        }
        // ---- stage B raw fp32 ----
        {
            const float* srcw = g_w + (size_t)kh*3*48*64;
            for (int i = tid; i < 3*48*64; i += 256) {
                int co = i & 63;
                int rest = i >> 6;
                int ci = rest % 48;
                int kw = rest / 48;
                sB[kw*SB_KW + ci*BP + co] = __ldg(srcw + i);
            }
        }
        __syncthreads();

        #pragma unroll
        for (int kw = 0; kw < 3; kw++) {
            const float* apb = pV + (mg*32 + kw + g)*AP + c;
            const float* bkw = sB + kw*SB_KW + nh*32 + g;
            #pragma unroll 2
            for (int ks = 0; ks < 6; ks++) {
                const int k0 = ks*8;
                // ---- A fragments: rows g,g+8,g+16,g+24; cols k0+c, k0+c+4 ----
                float v0 = apb[k0],             v1 = apb[k0 + 8*AP];
                float v2 = apb[k0 + 4],         v3 = apb[k0 + 8*AP + 4];
                float v4 = apb[k0 + 16*AP],     v5 = apb[k0 + 24*AP];
                float v6 = apb[k0 + 16*AP + 4], v7 = apb[k0 + 24*AP + 4];
                uint32_t h0 = __float_as_uint(v0) & TF32_MASK;
                uint32_t h1 = __float_as_uint(v1) & TF32_MASK;
                uint32_t h2 = __float_as_uint(v2) & TF32_MASK;
                uint32_t h3 = __float_as_uint(v3) & TF32_MASK;
                uint32_t h4 = __float_as_uint(v4) & TF32_MASK;
                uint32_t h5 = __float_as_uint(v5) & TF32_MASK;
                uint32_t h6 = __float_as_uint(v6) & TF32_MASK;
                uint32_t h7 = __float_as_uint(v7) & TF32_MASK;
                uint32_t l0 = __float_as_uint(v0 - __uint_as_float(h0));
                uint32_t l1 = __float_as_uint(v1 - __uint_as_float(h1));
                uint32_t l2 = __float_as_uint(v2 - __uint_as_float(h2));
                uint32_t l3 = __float_as_uint(v3 - __uint_as_float(h3));
                uint32_t l4 = __float_as_uint(v4 - __uint_as_float(h4));
                uint32_t l5 = __float_as_uint(v5 - __uint_as_float(h5));
                uint32_t l6 = __float_as_uint(v6 - __uint_as_float(h6));
                uint32_t l7 = __float_as_uint(v7 - __uint_as_float(h7));

                // ---- B fragments: load + split all 4 N-tiles up front ----
                const float* bp = bkw + (k0 + c)*BP;
                uint32_t bh0[4], bh1[4], bl0[4], bl1[4];
                #pragma unroll
                for (int nt = 0; nt < 4; nt++) {
                    float r0 = bp[nt*8];
                    float r1 = bp[4*BP + nt*8];
                    bh0[nt] = __float_as_uint(r0) & TF32_MASK;
                    bh1[nt] = __float_as_uint(r1) & TF32_MASK;
                    bl0[nt] = __float_as_uint(r0 - __uint_as_float(bh0[nt]));
                    bl1[nt] = __float_as_uint(r1 - __uint_as_float(bh1[nt]));
                }

                // ---- term-major MMAs: same-C reuse distance = 8 ----
                #pragma unroll
                for (int nt = 0; nt < 4; nt++) {          // Ahi * Bhi
                    mma8(C[0][nt], h0, h1, h2, h3, bh0[nt], bh1[nt]);
                    mma8(C[1][nt], h4, h5, h6, h7, bh0[nt], bh1[nt]);
                }
                #pragma unroll
                for (int nt = 0; nt < 4; nt++) {          // Ahi * Blo
                    mma8(C[0][nt], h0, h1, h2, h3, bl0[nt], bl1[nt]);
                    mma8(C[1][nt], h4, h5, h6, h7, bl0[nt], bl1[nt]);
                }
                #pragma unroll
                for (int nt = 0; nt < 4; nt++) {          // Alo * Bhi
                    mma8(C[0][nt], l0, l1, l2, l3, bh0[nt], bh1[nt]);
                    mma8(C[1][nt], l4, l5, l6, l7, bh0[nt], bh1[nt]);
                }
            }
        }
        __syncthreads();
    }

    // ---- write logits (single plane; each output owned by one warp) ----
    #pragma unroll
    for (int m = 0; m < 2; m++) {
        int px0 = mg*32 + m*16 + g;
        #pragma unroll
        for (int nt = 0; nt < 4; nt++) {
            int colb = nh*32 + nt*8 + 2*c;
            *reinterpret_cast<float2*>(LG + px0*LP + colb)     = make_float2(C[m][nt][0], C[m][nt][1]);
            *reinterpret_cast<float2*>(LG + (px0+8)*LP + colb) = make_float2(C[m][nt][2], C[m][nt][3]);
        }
    }
    __syncthreads();

    // ---- softmax + tanh: 2 threads/pixel, shfl combine ----
    const int px = tid >> 1;
    const int hf = tid & 1;
    const float* l0p = LG + px*LP + (hf << 5);
    const float* mb  = sbias + (hf << 5);

    float ev[32];
    float mx = -3.4e38f;
    #pragma unroll
    for (int i = 0; i < 32; i++) {
        float v = l0p[i] + mb[i];
        ev[i] = v;
        mx = fmaxf(mx, v);
    }
    mx = fmaxf(mx, __shfl_xor_sync(0xFFFFFFFFu, mx, 1));
    float s = 0.0f;
    #pragma unroll
    for (int i = 0; i < 32; i++) {
        float e = __expf(ev[i] - mx);
        ev[i] = e;
        s += e;
    }
    s += __shfl_xor_sync(0xFFFFFFFFu, s, 1);
    float inv = __fdividef(1.0f, s);

    float* ob = out + (size_t)b*COUT*HW + (size_t)h*WW + px + (size_t)(hf << 5)*HW;
    #pragma unroll
    for (int i = 0; i < 32; i++) {
        float p = ev[i] * inv;
        float t = __expf(-2.0f * p);
        ob[(size_t)i*HW] = __fdividef(1.0f - t, 1.0f + t);
    }
}

// ============================================================
extern "C" void kernel_launch(void* const* d_in, const int* in_sizes, int n_in,
                              void* d_out, int out_size) {
    const float* x      = (const float*)d_in[0];
    const float* wsum   = (const float*)d_in[1];
    const float* wfront = (const float*)d_in[2];
    const float* wback  = (const float*)d_in[3];
    const float* bias   = (const float*)d_in[4];
    float* out = (float*)d_out;

    cudaFuncSetAttribute(conv_mma, cudaFuncAttributeMaxDynamicSharedMemorySize, SMEM_BYTES);

    prep_all<<<DS_BLOCKS + (3*3*48*64 + 255)/256, 256>>>(x, wsum, wfront, wback);
    dim3 grid(HH, B);
    conv_mma<<<grid, 256, SMEM_BYTES>>>(x, bias, out);
}

// round 12
// speedup vs baseline: 2.2521x; 1.1217x over previous
#include <cuda_runtime.h>
#include <cstdint>

#define B 16
#define CIN 16
#define DD 16
#define HH 128
#define WW 128
#define COUT 64
#define HW (HH*WW)

// ---- device scratch ----
__device__ float g_s[B*CIN*HW];          // depth-summed x
__device__ float g_w[3*3*48*64];         // folded fp32 weights [kh][kw][ci][co]

// pack two floats into bf16x2 (lo -> low half, hi -> high half), round-nearest
__device__ __forceinline__ uint32_t pack2(float lo, float hi){
    uint32_t r; asm("cvt.rn.bf16x2.f32 %0, %1, %2;" : "=r"(r) : "f"(hi), "f"(lo)); return r;
}
// 2-term bf16 split of a float2 (adjacent-k pair): h = rn-bf16 pair, l = residual pair
__device__ __forceinline__ void split2(float2 p, uint32_t& h, uint32_t& l){
    h = pack2(p.x, p.y);
    float he = __uint_as_float(h << 16);
    float ho = __uint_as_float(h & 0xFFFF0000u);
    l = pack2(p.x - he, p.y - ho);
}

// m16n8k16 row.col bf16 MMA, accumulate in place
__device__ __forceinline__ void mma16(float* d,
                                      uint32_t a0, uint32_t a1, uint32_t a2, uint32_t a3,
                                      uint32_t b0, uint32_t b1){
    asm("mma.sync.aligned.m16n8k16.row.col.f32.bf16.bf16.f32 "
        "{%0,%1,%2,%3},{%4,%5,%6,%7},{%8,%9},{%0,%1,%2,%3};"
        : "+f"(d[0]), "+f"(d[1]), "+f"(d[2]), "+f"(d[3])
        : "r"(a0), "r"(a1), "r"(a2), "r"(a3), "r"(b0), "r"(b1));
}

// ============================================================
// Kernel A: depth sum + weight prep (merged)
// ============================================================
#define DS_BLOCKS (B*CIN*(HW/4)/256)      // 8192
__global__ void prep_all(const float* __restrict__ x,
                         const float* __restrict__ wsum,
                         const float* __restrict__ wfront,
                         const float* __restrict__ wback) {
    int bid = blockIdx.x;
    int tid = threadIdx.x;
    if (bid < DS_BLOCKS) {
        int i = bid*256 + tid;
        int bc = i / (HW/4);
        int r  = i - bc*(HW/4);
        const float4* p = reinterpret_cast<const float4*>(x) + (size_t)bc*DD*(HW/4) + r;
        float4 acc = p[0];
        #pragma unroll
        for (int z = 1; z < DD; z++) {
            float4 v = p[(size_t)z*(HW/4)];
            acc.x += v.x; acc.y += v.y; acc.z += v.z; acc.w += v.w;
        }
        reinterpret_cast<float4*>(g_s)[(size_t)bc*(HW/4) + r] = acc;
    } else {
        int idx = (bid - DS_BLOCKS)*256 + tid;
        if (idx < 3*3*48*64) {
            int co   = idx & 63;
            int rest = idx >> 6;
            int ci   = rest % 48;
            int rest2 = rest / 48;
            int kw = rest2 % 3;
            int kh = rest2 / 3;
            int grp = ci >> 4, ch = ci & 15;
            const float* src = grp==0 ? wsum : (grp==1 ? wfront : wback);
            float v = src[(co*CIN + ch)*9 + kh*3 + kw];
            if (grp) v = -v;
            g_w[idx] = v;
        }
    }
}

// ============================================================
// Kernel B: 3-product bf16 (2-term split) implicit conv + softmax + tanh
//   CTA = image row (b,h): M=128 px, N=64 co. 256 threads, 8 warps, 3 CTAs/SM.
//   Warp tile M32 x N32: mg = wid&3, nh = wid>>2.
//   mma.m16n8k16.bf16: K=16/instr -> 648 MMA/warp (half of tf32 k8).
//   A,B split in registers: hi = rn-bf16 (cvt.rn.bf16x2 pair), lo = residual.
//   Adjacent-k pairs -> all fragment loads are LDS.64.
//   Pitch 56: f2-bank (12g+c) mod 16 permutation -> conflict-free.
//   smem (floats):
//     [0,64)            bias
//     [64, +10752)      B: [kw3][co64][ci48 pad56] fp32
//     [10816, +7280)    patch v: [col130][ci48 pad56]
//     logits alias B region after MMAs: [px128][co] pitch 68 (8704 <= 10752)
// ============================================================
#define PP 56
#define SB_CO 56
#define SB_KW (64*SB_CO)           // 3584
#define OFF_B 64
#define OFF_PV (OFF_B + 3*SB_KW)   // 10816
#define LP 68
#define SMEM_FLOATS (OFF_PV + 130*PP)  // 18096
#define SMEM_BYTES (SMEM_FLOATS*4)     // 72384

__global__ void __launch_bounds__(256, 3)
conv_mma(const float* __restrict__ x,
         const float* __restrict__ bias,
         float* __restrict__ out) {
    extern __shared__ float sm[];
    float* sbias = sm;
    float* sB    = sm + OFF_B;
    float* pV    = sm + OFF_PV;
    float* LG    = sm + OFF_B;       // logits alias (B region dead after MMAs)

    const int tid = threadIdx.x;
    const int h = blockIdx.x;
    const int b = blockIdx.y;

    if (tid < 64) sbias[tid] = bias[tid];

    const int lane = tid & 31, wid = tid >> 5;
    const int g = lane >> 2, c = lane & 3;
    const int mg = wid & 3, nh = wid >> 2;

    float C[2][4][4];
    #pragma unroll
    for (int m = 0; m < 2; m++)
        #pragma unroll
        for (int nt = 0; nt < 4; nt++)
            #pragma unroll
            for (int r = 0; r < 4; r++) C[m][nt][r] = 0.0f;

    for (int kh = 0; kh < 3; kh++) {
        const int row = h + kh - 1;
        const bool valid = (unsigned)row < HH;

        // ---- build A patch (raw fp32), [col][ci] pitch 56 ----
        const float* ps = g_s + (size_t)b*CIN*HW + (size_t)row*WW;
        const float* pf = x  + (size_t)b*CIN*DD*HW + (size_t)row*WW;
        for (int i = tid; i < 48*130; i += 256) {
            int ci = i / 130, r = i - ci*130;
            int col = r - 1;
            float v = 0.0f;
            if (valid && (unsigned)col < WW) {
                int grp = ci >> 4, ch = ci & 15;
                const float* src = (grp == 0) ? ps + (size_t)ch*HW
                                 : pf + ((size_t)ch*DD + (grp == 1 ? 0 : DD-1))*HW;
                v = __ldg(src + col);
            }
            pV[r*PP + ci] = v;
        }
        // ---- stage B raw fp32, [kw][co][ci] pitch 56 ----
        {
            const float* srcw = g_w + (size_t)kh*3*48*64;
            for (int i = tid; i < 3*48*64; i += 256) {
                int co = i & 63;
                int rest = i >> 6;
                int ci = rest % 48;
                int kw = rest / 48;
                sB[kw*SB_KW + co*SB_CO + ci] = __ldg(srcw + i);
            }
        }
        __syncthreads();

        #pragma unroll
        for (int kw = 0; kw < 3; kw++) {
            const int rbase = mg*32 + kw + g;
            const float* bkw = sB + kw*SB_KW + (nh*32 + g)*SB_CO + 2*c;
            #pragma unroll
            for (int ks = 0; ks < 3; ks++) {
                const int k0 = ks*16;
                // ---- A fragments: 8 LDS.64, split hi/lo ----
                uint32_t ah[2][4], al[2][4];
                #pragma unroll
                for (int m = 0; m < 2; m++)
                    #pragma unroll
                    for (int k2 = 0; k2 < 2; k2++)
                        #pragma unroll
                        for (int rr = 0; rr < 2; rr++) {
                            float2 p = *reinterpret_cast<const float2*>(
                                pV + (rbase + m*16 + rr*8)*PP + k0 + k2*8 + 2*c);
                            split2(p, ah[m][k2*2+rr], al[m][k2*2+rr]);
                        }
                // ---- B fragments: 8 LDS.64, split hi/lo ----
                uint32_t bh[4][2], bl[4][2];
                #pragma unroll
                for (int nt = 0; nt < 4; nt++)
                    #pragma unroll
                    for (int k2 = 0; k2 < 2; k2++) {
                        float2 q = *reinterpret_cast<const float2*>(
                            bkw + nt*8*SB_CO + k0 + k2*8);
                        split2(q, bh[nt][k2], bl[nt][k2]);
                    }
                // ---- term-major MMAs (reuse distance 8) ----
                #pragma unroll
                for (int nt = 0; nt < 4; nt++) {          // Ahi * Bhi
                    mma16(C[0][nt], ah[0][0], ah[0][1], ah[0][2], ah[0][3], bh[nt][0], bh[nt][1]);
                    mma16(C[1][nt], ah[1][0], ah[1][1], ah[1][2], ah[1][3], bh[nt][0], bh[nt][1]);
                }
                #pragma unroll
                for (int nt = 0; nt < 4; nt++) {          // Ahi * Blo
                    mma16(C[0][nt], ah[0][0], ah[0][1], ah[0][2], ah[0][3], bl[nt][0], bl[nt][1]);
                    mma16(C[1][nt], ah[1][0], ah[1][1], ah[1][2], ah[1][3], bl[nt][0], bl[nt][1]);
                }
                #pragma unroll
                for (int nt = 0; nt < 4; nt++) {          // Alo * Bhi
                    mma16(C[0][nt], al[0][0], al[0][1], al[0][2], al[0][3], bh[nt][0], bh[nt][1]);
                    mma16(C[1][nt], al[1][0], al[1][1], al[1][2], al[1][3], bh[nt][0], bh[nt][1]);
                }
            }
        }
        __syncthreads();
    }

    // ---- write logits (single plane; each output owned by one warp) ----
    #pragma unroll
    for (int m = 0; m < 2; m++) {
        int px0 = mg*32 + m*16 + g;
        #pragma unroll
        for (int nt = 0; nt < 4; nt++) {
            int colb = nh*32 + nt*8 + 2*c;
            *reinterpret_cast<float2*>(LG + px0*LP + colb)     = make_float2(C[m][nt][0], C[m][nt][1]);
            *reinterpret_cast<float2*>(LG + (px0+8)*LP + colb) = make_float2(C[m][nt][2], C[m][nt][3]);
        }
    }
    __syncthreads();

    // ---- softmax + tanh: 2 threads/pixel, shfl combine ----
    const int px = tid >> 1;
    const int hf = tid & 1;
    const float* l0p = LG + px*LP + (hf << 5);
    const float* mb  = sbias + (hf << 5);

    float ev[32];
    float mx = -3.4e38f;
    #pragma unroll
    for (int i = 0; i < 32; i++) {
        float v = l0p[i] + mb[i];
        ev[i] = v;
        mx = fmaxf(mx, v);
    }
    mx = fmaxf(mx, __shfl_xor_sync(0xFFFFFFFFu, mx, 1));
    float s = 0.0f;
    #pragma unroll
    for (int i = 0; i < 32; i++) {
        float e = __expf(ev[i] - mx);
        ev[i] = e;
        s += e;
    }
    s += __shfl_xor_sync(0xFFFFFFFFu, s, 1);
    float inv = __fdividef(1.0f, s);

    float* ob = out + (size_t)b*COUT*HW + (size_t)h*WW + px + (size_t)(hf << 5)*HW;
    #pragma unroll
    for (int i = 0; i < 32; i++) {
        float p = ev[i] * inv;
        float t = __expf(-2.0f * p);
        ob[(size_t)i*HW] = __fdividef(1.0f - t, 1.0f + t);
    }
}

// ============================================================
extern "C" void kernel_launch(void* const* d_in, const int* in_sizes, int n_in,
                              void* d_out, int out_size) {
    const float* x      = (const float*)d_in[0];
    const float* wsum   = (const float*)d_in[1];
    const float* wfront = (const float*)d_in[2];
    const float* wback  = (const float*)d_in[3];
    const float* bias   = (const float*)d_in[4];
    float* out = (float*)d_out;

    cudaFuncSetAttribute(conv_mma, cudaFuncAttributeMaxDynamicSharedMemorySize, SMEM_BYTES);

    prep_all<<<DS_BLOCKS + (3*3*48*64 + 255)/256, 256>>>(x, wsum, wfront, wback);
    dim3 grid(HH, B);
    conv_mma<<<grid, 256, SMEM_BYTES>>>(x, bias, out);
}

// round 13
// speedup vs baseline: 3.0697x; 1.3631x over previous
#include <cuda_runtime.h>
#include <cstdint>

#define B 16
#define CIN 16
#define DD 16
#define HH 128
#define WW 128
#define COUT 64
#define HW (HH*WW)

// ---- device scratch ----
__device__ float g_s[B*CIN*HW];            // depth-summed x
__device__ uint32_t g_wbh[3*3*64*24];      // weight bf16x2 hi [kh][kw][co][kpair]
__device__ uint32_t g_wbl[3*3*64*24];      // weight bf16x2 lo

// pack two floats into bf16x2 (x -> low half, y -> high half), round-nearest
__device__ __forceinline__ uint32_t pack2(float lo, float hi){
    uint32_t r; asm("cvt.rn.bf16x2.f32 %0, %1, %2;" : "=r"(r) : "f"(hi), "f"(lo)); return r;
}
// 2-term bf16 split of an adjacent-k float2 pair
__device__ __forceinline__ void split2(float2 p, uint32_t& h, uint32_t& l){
    h = pack2(p.x, p.y);
    float he = __uint_as_float(h << 16);
    float ho = __uint_as_float(h & 0xFFFF0000u);
    l = pack2(p.x - he, p.y - ho);
}

// m16n8k16 row.col bf16 MMA, accumulate in place
__device__ __forceinline__ void mma16(float* d,
                                      uint32_t a0, uint32_t a1, uint32_t a2, uint32_t a3,
                                      uint32_t b0, uint32_t b1){
    asm("mma.sync.aligned.m16n8k16.row.col.f32.bf16.bf16.f32 "
        "{%0,%1,%2,%3},{%4,%5,%6,%7},{%8,%9},{%0,%1,%2,%3};"
        : "+f"(d[0]), "+f"(d[1]), "+f"(d[2]), "+f"(d[3])
        : "r"(a0), "r"(a1), "r"(a2), "r"(a3), "r"(b0), "r"(b1));
}

// ============================================================
// Kernel A: depth sum + weight bf16 hi/lo prep (merged)
// ============================================================
#define DS_BLOCKS (B*CIN*(HW/4)/256)      // 8192
#define NWPAIR (3*3*64*24)                // 13824
__global__ void prep_all(const float* __restrict__ x,
                         const float* __restrict__ wsum,
                         const float* __restrict__ wfront,
                         const float* __restrict__ wback) {
    int bid = blockIdx.x;
    int tid = threadIdx.x;
    if (bid < DS_BLOCKS) {
        int i = bid*256 + tid;
        int bc = i / (HW/4);
        int r  = i - bc*(HW/4);
        const float4* p = reinterpret_cast<const float4*>(x) + (size_t)bc*DD*(HW/4) + r;
        float4 acc = p[0];
        #pragma unroll
        for (int z = 1; z < DD; z++) {
            float4 v = p[(size_t)z*(HW/4)];
            acc.x += v.x; acc.y += v.y; acc.z += v.z; acc.w += v.w;
        }
        reinterpret_cast<float4*>(g_s)[(size_t)bc*(HW/4) + r] = acc;
    } else {
        int idx = (bid - DS_BLOCKS)*256 + tid;
        if (idx < NWPAIR) {
            int kp = idx % 24;
            int co = (idx / 24) & 63;
            int kw = (idx / (24*64)) % 3;
            int kh = idx / (24*64*3);
            float vp[2];
            #pragma unroll
            for (int j = 0; j < 2; j++) {
                int ci = 2*kp + j;
                int grp = ci >> 4, ch = ci & 15;
                const float* src = grp==0 ? wsum : (grp==1 ? wfront : wback);
                float v = src[(co*CIN + ch)*9 + kh*3 + kw];
                vp[j] = grp ? -v : v;
            }
            uint32_t hh, ll;
            split2(make_float2(vp[0], vp[1]), hh, ll);
            g_wbh[idx] = hh;
            g_wbl[idx] = ll;
        }
    }
}

// ============================================================
// Kernel B: 3-product bf16 implicit conv + softmax + tanh
//   CTA = image row (b,h): M=128 px, N=64 co. 256 threads, 8 warps, 3 CTAs/SM.
//   Warp tile M32 x N32: mg = wid&3, nh = wid>>2.
//   PRE-SPLIT hi/lo bf16x2 planes in smem; hot loop = LDS.32 + MMA only.
//   Pitch 28 uint32: bank (28g+c) mod 32 distinct over all 32 lanes -> cf.
//   smem (floats/uint32):
//     [0,64)            bias
//     [64, +5376)       B hi: [kw3][co64][kpair24 pad28] bf16x2
//     [5440, +5376)     B lo
//     [10816, +3640)    A hi: [col130][kpair24 pad28] bf16x2
//     [14456, +3640)    A lo
//     logits alias B region after MMAs: [px128][co] pitch 68 (8704 <= 10752)
// ============================================================
#define KP 24
#define PP 28
#define SB_CO PP
#define SB_KW (64*PP)              // 1792
#define OFF_BH 64
#define OFF_BL (OFF_BH + 3*SB_KW)  // 5440
#define OFF_AH (OFF_BL + 3*SB_KW)  // 10816
#define OFF_AL (OFF_AH + 130*PP)   // 14456
#define LP 68
#define SMEM_FLOATS (OFF_AL + 130*PP)  // 18096
#define SMEM_BYTES (SMEM_FLOATS*4)     // 72384

__global__ void __launch_bounds__(256, 3)
conv_mma(const float* __restrict__ x,
         const float* __restrict__ bias,
         float* __restrict__ out) {
    extern __shared__ float sm[];
    float* sbias   = sm;
    uint32_t* sBH  = reinterpret_cast<uint32_t*>(sm + OFF_BH);
    uint32_t* sBL  = reinterpret_cast<uint32_t*>(sm + OFF_BL);
    uint32_t* sAH  = reinterpret_cast<uint32_t*>(sm + OFF_AH);
    uint32_t* sAL  = reinterpret_cast<uint32_t*>(sm + OFF_AL);
    float* LG      = sm + OFF_BH;    // logits alias (B region dead after MMAs)

    const int tid = threadIdx.x;
    const int h = blockIdx.x;
    const int b = blockIdx.y;

    if (tid < 64) sbias[tid] = bias[tid];

    const int lane = tid & 31, wid = tid >> 5;
    const int g = lane >> 2, c = lane & 3;
    const int mg = wid & 3, nh = wid >> 2;

    float C[2][4][4];
    #pragma unroll
    for (int m = 0; m < 2; m++)
        #pragma unroll
        for (int nt = 0; nt < 4; nt++)
            #pragma unroll
            for (int r = 0; r < 4; r++) C[m][nt][r] = 0.0f;

    for (int kh = 0; kh < 3; kh++) {
        const int row = h + kh - 1;
        const bool valid = (unsigned)row < HH;

        // ---- build A planes: split at build time, once per element ----
        const float* ps = g_s + (size_t)b*CIN*HW + (size_t)row*WW;
        const float* pf = x  + (size_t)b*CIN*DD*HW + (size_t)row*WW;
        for (int i = tid; i < KP*130; i += 256) {
            int kp = i / 130, r = i - kp*130;
            int col = r - 1;
            float va = 0.0f, vb = 0.0f;
            if (valid && (unsigned)col < WW) {
                #pragma unroll
                for (int j = 0; j < 2; j++) {
                    int ci = 2*kp + j;
                    int grp = ci >> 4, ch = ci & 15;
                    const float* src = (grp == 0) ? ps + (size_t)ch*HW
                                     : pf + ((size_t)ch*DD + (grp == 1 ? 0 : DD-1))*HW;
                    float v = __ldg(src + col);
                    if (j == 0) va = v; else vb = v;
                }
            }
            uint32_t hh, ll;
            split2(make_float2(va, vb), hh, ll);
            sAH[r*PP + kp] = hh;
            sAL[r*PP + kp] = ll;
        }
        // ---- stage B planes (pre-split in gmem) ----
        {
            const uint32_t* wh = g_wbh + (size_t)kh*3*64*KP;
            const uint32_t* wl = g_wbl + (size_t)kh*3*64*KP;
            for (int i = tid; i < 3*64*KP; i += 256) {
                int kp = i % KP;
                int co = (i / KP) & 63;
                int kw = i / (KP*64);
                int d = kw*SB_KW + co*SB_CO + kp;
                sBH[d] = __ldg(wh + i);
                sBL[d] = __ldg(wl + i);
            }
        }
        __syncthreads();

        #pragma unroll
        for (int kw = 0; kw < 3; kw++) {
            const uint32_t* aH = sAH + (mg*32 + kw + g)*PP + c;
            const uint32_t* aL = sAL + (mg*32 + kw + g)*PP + c;
            const uint32_t* bH = sBH + kw*SB_KW + (nh*32 + g)*SB_CO + c;
            const uint32_t* bL = sBL + kw*SB_KW + (nh*32 + g)*SB_CO + c;
            #pragma unroll
            for (int ks = 0; ks < 3; ks++) {
                const int k0 = ks*8;   // kpair offset
                // ---- A fragments (LDS.32, no splits) ----
                uint32_t ah[2][4], al[2][4];
                #pragma unroll
                for (int m = 0; m < 2; m++) {
                    ah[m][0] = aH[(m*16    )*PP + k0    ];
                    ah[m][1] = aH[(m*16 + 8)*PP + k0    ];
                    ah[m][2] = aH[(m*16    )*PP + k0 + 4];
                    ah[m][3] = aH[(m*16 + 8)*PP + k0 + 4];
                    al[m][0] = aL[(m*16    )*PP + k0    ];
                    al[m][1] = aL[(m*16 + 8)*PP + k0    ];
                    al[m][2] = aL[(m*16    )*PP + k0 + 4];
                    al[m][3] = aL[(m*16 + 8)*PP + k0 + 4];
                }
                // ---- B fragments ----
                uint32_t bh[4][2], bl[4][2];
                #pragma unroll
                for (int nt = 0; nt < 4; nt++) {
                    bh[nt][0] = bH[nt*8*SB_CO + k0];
                    bh[nt][1] = bH[nt*8*SB_CO + k0 + 4];
                    bl[nt][0] = bL[nt*8*SB_CO + k0];
                    bl[nt][1] = bL[nt*8*SB_CO + k0 + 4];
                }
                // ---- term-major MMAs ----
                #pragma unroll
                for (int nt = 0; nt < 4; nt++) {          // Ahi * Bhi
                    mma16(C[0][nt], ah[0][0], ah[0][1], ah[0][2], ah[0][3], bh[nt][0], bh[nt][1]);
                    mma16(C[1][nt], ah[1][0], ah[1][1], ah[1][2], ah[1][3], bh[nt][0], bh[nt][1]);
                }
                #pragma unroll
                for (int nt = 0; nt < 4; nt++) {          // Ahi * Blo
                    mma16(C[0][nt], ah[0][0], ah[0][1], ah[0][2], ah[0][3], bl[nt][0], bl[nt][1]);
                    mma16(C[1][nt], ah[1][0], ah[1][1], ah[1][2], ah[1][3], bl[nt][0], bl[nt][1]);
                }
                #pragma unroll
                for (int nt = 0; nt < 4; nt++) {          // Alo * Bhi
                    mma16(C[0][nt], al[0][0], al[0][1], al[0][2], al[0][3], bh[nt][0], bh[nt][1]);
                    mma16(C[1][nt], al[1][0], al[1][1], al[1][2], al[1][3], bh[nt][0], bh[nt][1]);
                }
            }
        }
        __syncthreads();
    }

    // ---- write logits (single plane; each output owned by one warp) ----
    #pragma unroll
    for (int m = 0; m < 2; m++) {
        int px0 = mg*32 + m*16 + g;
        #pragma unroll
        for (int nt = 0; nt < 4; nt++) {
            int colb = nh*32 + nt*8 + 2*c;
            *reinterpret_cast<float2*>(LG + px0*LP + colb)     = make_float2(C[m][nt][0], C[m][nt][1]);
            *reinterpret_cast<float2*>(LG + (px0+8)*LP + colb) = make_float2(C[m][nt][2], C[m][nt][3]);
        }
    }
    __syncthreads();

    // ---- softmax + tanh: 2 threads/pixel, shfl combine ----
    const int px = tid >> 1;
    const int hf = tid & 1;
    const float* l0p = LG + px*LP + (hf << 5);
    const float* mb  = sbias + (hf << 5);

    float ev[32];
    float mx = -3.4e38f;
    #pragma unroll
    for (int i = 0; i < 32; i++) {
        float v = l0p[i] + mb[i];
        ev[i] = v;
        mx = fmaxf(mx, v);
    }
    mx = fmaxf(mx, __shfl_xor_sync(0xFFFFFFFFu, mx, 1));
    float s = 0.0f;
    #pragma unroll
    for (int i = 0; i < 32; i++) {
        float e = __expf(ev[i] - mx);
        ev[i] = e;
        s += e;
    }
    s += __shfl_xor_sync(0xFFFFFFFFu, s, 1);
    float inv = __fdividef(1.0f, s);

    float* ob = out + (size_t)b*COUT*HW + (size_t)h*WW + px + (size_t)(hf << 5)*HW;
    #pragma unroll
    for (int i = 0; i < 32; i++) {
        float p = ev[i] * inv;
        float t = __expf(-2.0f * p);
        ob[(size_t)i*HW] = __fdividef(1.0f - t, 1.0f + t);
    }
}

// ============================================================
extern "C" void kernel_launch(void* const* d_in, const int* in_sizes, int n_in,
                              void* d_out, int out_size) {
    const float* x      = (const float*)d_in[0];
    const float* wsum   = (const float*)d_in[1];
    const float* wfront = (const float*)d_in[2];
    const float* wback  = (const float*)d_in[3];
    const float* bias   = (const float*)d_in[4];
    float* out = (float*)d_out;

    cudaFuncSetAttribute(conv_mma, cudaFuncAttributeMaxDynamicSharedMemorySize, SMEM_BYTES);

    prep_all<<<DS_BLOCKS + (NWPAIR + 255)/256, 256>>>(x, wsum, wfront, wback);
    dim3 grid(HH, B);
    conv_mma<<<grid, 256, SMEM_BYTES>>>(x, bias, out);
}